// round 3
// baseline (speedup 1.0000x reference)
#include <cuda_runtime.h>
#include <cuda_bf16.h>

#define NUM_FEATURES 64
#define MAX_CAV 5
#define NX 704
#define NY 200
#define NUM_PIXELS (NY * NX)          // 140800
#define TOTAL (MAX_CAV * NUM_PIXELS)  // 704000
#define N_PILLARS 60000
#define NGROUPS (NUM_PIXELS / 4)      // 35200 groups of 4 pixels

// Inverse map: pixel -> pillar index + 1 (0 = empty).
// Zero-initialized by the CUDA runtime; the gather kernel resets entries to 0
// after consuming them, so every kernel_launch call sees an all-zero map.
__device__ int g_pixmap[TOTAL];

// Kernel A: scatter (pillar+1) into the pixmap (indices are a permutation -> no collisions).
__global__ void __launch_bounds__(256) pp_build_pixmap(const int* __restrict__ vc)
{
    int n = blockIdx.x * blockDim.x + threadIdx.x;
    if (n >= N_PILLARS) return;
    int4 co = __ldg(reinterpret_cast<const int4*>(vc) + n);  // (b, z, y, x)
    g_pixmap[co.x * NUM_PIXELS + co.z * NX + co.w] = n + 1;
}

// Kernel B: gather. One thread per (b, 4-pixel group). Writes all 64 channel
// planes with float4 (st.128) stores; resets its pixmap entry to zero.
__global__ void __launch_bounds__(256) pp_gather(
    const float* __restrict__ feat,   // [N, 64]
    float* __restrict__ out)          // [5, 64, 200, 704]
{
    int g = blockIdx.x * blockDim.x + threadIdx.x;     // group id 0..NGROUPS-1
    if (g >= NGROUPS) return;
    int b = blockIdx.y;                                // 0..4

    int4* pm_ptr = reinterpret_cast<int4*>(g_pixmap) + (size_t)b * NGROUPS + g;
    int4 pm = *pm_ptr;
    *pm_ptr = make_int4(0, 0, 0, 0);                   // reset for next call

    // out plane-group base: channel c store address = obase + c*NUM_PIXELS/4 (float4 units)
    float4* obase = reinterpret_cast<float4*>(out)
                  + (size_t)b * NUM_FEATURES * NGROUPS + g;

    const float4 zero = make_float4(0.f, 0.f, 0.f, 0.f);

    if ((pm.x | pm.y | pm.z | pm.w) == 0) {
        // Fast path (~70% of groups): stream 64 zero float4 stores, no loads.
        #pragma unroll
        for (int c = 0; c < NUM_FEATURES; c++) {
            obase[(size_t)c * NGROUPS] = zero;
        }
        return;
    }

    // Slow path: up to 4 distinct pillars; process channels 4 at a time,
    // transposing 4 feature-float4s into 4 pixel-float4s.
    const float4* f0 = reinterpret_cast<const float4*>(feat) + (size_t)(pm.x - 1) * (NUM_FEATURES / 4);
    const float4* f1 = reinterpret_cast<const float4*>(feat) + (size_t)(pm.y - 1) * (NUM_FEATURES / 4);
    const float4* f2 = reinterpret_cast<const float4*>(feat) + (size_t)(pm.z - 1) * (NUM_FEATURES / 4);
    const float4* f3 = reinterpret_cast<const float4*>(feat) + (size_t)(pm.w - 1) * (NUM_FEATURES / 4);

    #pragma unroll
    for (int c4 = 0; c4 < NUM_FEATURES / 4; c4++) {
        float4 a = (pm.x > 0) ? __ldg(f0 + c4) : zero;
        float4 bb = (pm.y > 0) ? __ldg(f1 + c4) : zero;
        float4 cc = (pm.z > 0) ? __ldg(f2 + c4) : zero;
        float4 dd = (pm.w > 0) ? __ldg(f3 + c4) : zero;

        obase[(size_t)(4 * c4 + 0) * NGROUPS] = make_float4(a.x, bb.x, cc.x, dd.x);
        obase[(size_t)(4 * c4 + 1) * NGROUPS] = make_float4(a.y, bb.y, cc.y, dd.y);
        obase[(size_t)(4 * c4 + 2) * NGROUPS] = make_float4(a.z, bb.z, cc.z, dd.z);
        obase[(size_t)(4 * c4 + 3) * NGROUPS] = make_float4(a.w, bb.w, cc.w, dd.w);
    }
}

extern "C" void kernel_launch(void* const* d_in, const int* in_sizes, int n_in,
                              void* d_out, int out_size)
{
    const int*   vc   = (const int*)d_in[0];    // voxel_coords int32 [60000, 4]
    const float* feat = (const float*)d_in[1];  // pillar_features f32 [60000, 64]
    float* out = (float*)d_out;                 // [5, 64, 200, 704] f32

    pp_build_pixmap<<<(N_PILLARS + 255) / 256, 256>>>(vc);

    dim3 grid((NGROUPS + 255) / 256, MAX_CAV);  // (138, 5)
    pp_gather<<<grid, 256>>>(feat, out);
}

// round 4
// speedup vs baseline: 1.3044x; 1.3044x over previous
#include <cuda_runtime.h>
#include <cuda_bf16.h>

#define NUM_FEATURES 64
#define MAX_CAV 5
#define NX 704
#define NY 200
#define NUM_PIXELS (NY * NX)          // 140800
#define TOTAL (MAX_CAV * NUM_PIXELS)  // 704000
#define N_PILLARS 60000

// Inverse map: pixel -> pillar index + 1 (0 = empty).
// Zero-initialized at module load; the gather kernel resets each entry to 0
// after consuming it, so every kernel_launch call observes an all-zero map.
__device__ int g_pixmap[TOTAL];

// Kernel A: scatter (pillar+1) into the pixmap (indices are a permutation -> no collisions).
__global__ void __launch_bounds__(256) pp_build_pixmap(const int* __restrict__ vc)
{
    int n = blockIdx.x * blockDim.x + threadIdx.x;
    if (n >= N_PILLARS) return;
    int4 co = __ldg(reinterpret_cast<const int4*>(vc) + n);  // (b, z, y, x)
    g_pixmap[co.x * NUM_PIXELS + co.z * NX + co.w] = n + 1;
}

// Kernel B: gather. One thread per (b, pixel). Writes all 64 channel planes
// exactly once (coalesced 128B warp stores, streaming hint), resets its
// pixmap entry, reads the occupied pillar's 256B feature row contiguously.
__global__ void __launch_bounds__(256) pp_gather(
    const float* __restrict__ feat,   // [N, 64]
    float* __restrict__ out)          // [5, 64, 200, 704]
{
    int pix = blockIdx.x * blockDim.x + threadIdx.x;   // 0..NUM_PIXELS-1
    int b   = blockIdx.y;                              // 0..4

    int* pm_ptr = g_pixmap + (size_t)b * NUM_PIXELS + pix;
    int n1 = *pm_ptr;            // load early: ~600cyc DRAM latency to hide
    *pm_ptr = 0;                 // self-clear for the next call

    float* obase = out + (size_t)b * NUM_FEATURES * NUM_PIXELS + pix;

    if (n1 == 0) {
        // Empty pixel (~91%): stream 64 zero stores, no further loads.
        #pragma unroll
        for (int c = 0; c < NUM_FEATURES; c++) {
            __stcs(obase + (size_t)c * NUM_PIXELS, 0.0f);
        }
        return;
    }

    const float4* frow = reinterpret_cast<const float4*>(feat)
                       + (size_t)(n1 - 1) * (NUM_FEATURES / 4);
    #pragma unroll
    for (int c4 = 0; c4 < NUM_FEATURES / 4; c4++) {
        float4 f = __ldcs(frow + c4);
        __stcs(obase + (size_t)(c4 * 4 + 0) * NUM_PIXELS, f.x);
        __stcs(obase + (size_t)(c4 * 4 + 1) * NUM_PIXELS, f.y);
        __stcs(obase + (size_t)(c4 * 4 + 2) * NUM_PIXELS, f.z);
        __stcs(obase + (size_t)(c4 * 4 + 3) * NUM_PIXELS, f.w);
    }
}

extern "C" void kernel_launch(void* const* d_in, const int* in_sizes, int n_in,
                              void* d_out, int out_size)
{
    const int*   vc   = (const int*)d_in[0];    // voxel_coords int32 [60000, 4]
    const float* feat = (const float*)d_in[1];  // pillar_features f32 [60000, 64]
    float* out = (float*)d_out;                 // [5, 64, 200, 704] f32

    pp_build_pixmap<<<(N_PILLARS + 255) / 256, 256>>>(vc);

    dim3 grid(NUM_PIXELS / 256, MAX_CAV);   // (550, 5) — exact
    pp_gather<<<grid, 256>>>(feat, out);
}

// round 5
// speedup vs baseline: 1.3665x; 1.0476x over previous
#include <cuda_runtime.h>
#include <cuda_bf16.h>

#define NUM_FEATURES 64
#define MAX_CAV 5
#define NX 704
#define NY 200
#define NUM_PIXELS (NY * NX)          // 140800
#define TOTAL (MAX_CAV * NUM_PIXELS)  // 704000
#define N_PILLARS 60000
#define NGROUPS (NUM_PIXELS / 4)      // 35200 (= 1100 * 32, exact)

// Inverse map: pixel -> pillar index + 1 (0 = empty).
// Never cleared. Zero at module load; build overwrites current entries each
// call; gather validates every entry against voxel_coords, so stale entries
// (only possible if inputs changed) are rejected. Output is therefore a pure
// function of the current inputs.
__device__ int g_pixmap[TOTAL];

// Kernel A: scatter (pillar+1) into the pixmap (indices are a permutation -> no collisions).
__global__ void __launch_bounds__(256) pp_build_pixmap(const int* __restrict__ vc)
{
    int n = blockIdx.x * blockDim.x + threadIdx.x;
    if (n >= N_PILLARS) return;
    int4 co = __ldg(reinterpret_cast<const int4*>(vc) + n);  // (b, z, y, x)
    g_pixmap[co.x * NUM_PIXELS + co.z * NX + co.w] = n + 1;
}

// Kernel B: streaming gather.
//   thread = (b, channel c, 4-pixel group g);  lane == g % 32
//   -> warp store = 32 * float4 = 512B contiguous (st.128, full sectors)
//   -> pixmap/vc/feat reads are L2-resident across the 64 channel passes
__global__ void __launch_bounds__(256) pp_gather(
    const int*   __restrict__ vc,     // [N, 4]
    const float* __restrict__ feat,   // [N, 64]
    float*       __restrict__ out)    // [5, 64, 200, 704]
{
    int lane = threadIdx.x & 31;
    int w    = threadIdx.x >> 5;                 // warp in block: 0..7
    int g    = blockIdx.x * 32 + lane;           // 4-pixel group: 0..NGROUPS-1
    int c    = blockIdx.y * 8 + w;               // channel: 0..63
    int b    = blockIdx.z;                       // cav: 0..4

    int4 pm = __ldg(reinterpret_cast<const int4*>(g_pixmap)
                    + (size_t)b * NGROUPS + g);

    float4 v = make_float4(0.f, 0.f, 0.f, 0.f);

    if ((pm.x | pm.y | pm.z | pm.w) != 0) {
        int basepix = b * NUM_PIXELS + g * 4;    // flat index of sub-pixel 0

        if (pm.x > 0) {
            int n = pm.x - 1;
            int4 co = __ldg(reinterpret_cast<const int4*>(vc) + n);
            if (co.x * NUM_PIXELS + co.z * NX + co.w == basepix + 0)
                v.x = __ldg(feat + (size_t)n * NUM_FEATURES + c);
        }
        if (pm.y > 0) {
            int n = pm.y - 1;
            int4 co = __ldg(reinterpret_cast<const int4*>(vc) + n);
            if (co.x * NUM_PIXELS + co.z * NX + co.w == basepix + 1)
                v.y = __ldg(feat + (size_t)n * NUM_FEATURES + c);
        }
        if (pm.z > 0) {
            int n = pm.z - 1;
            int4 co = __ldg(reinterpret_cast<const int4*>(vc) + n);
            if (co.x * NUM_PIXELS + co.z * NX + co.w == basepix + 2)
                v.z = __ldg(feat + (size_t)n * NUM_FEATURES + c);
        }
        if (pm.w > 0) {
            int n = pm.w - 1;
            int4 co = __ldg(reinterpret_cast<const int4*>(vc) + n);
            if (co.x * NUM_PIXELS + co.z * NX + co.w == basepix + 3)
                v.w = __ldg(feat + (size_t)n * NUM_FEATURES + c);
        }
    }

    // Coalesced: lanes cover 32 consecutive float4s (512B per warp store).
    reinterpret_cast<float4*>(out)[((size_t)b * NUM_FEATURES + c) * NGROUPS + g] = v;
}

extern "C" void kernel_launch(void* const* d_in, const int* in_sizes, int n_in,
                              void* d_out, int out_size)
{
    const int*   vc   = (const int*)d_in[0];    // voxel_coords int32 [60000, 4]
    const float* feat = (const float*)d_in[1];  // pillar_features f32 [60000, 64]
    float* out = (float*)d_out;                 // [5, 64, 200, 704] f32

    pp_build_pixmap<<<(N_PILLARS + 255) / 256, 256>>>(vc);

    dim3 grid(NGROUPS / 32, NUM_FEATURES / 8, MAX_CAV);   // (1100, 8, 5)
    pp_gather<<<grid, 256>>>(vc, feat, out);
}

// round 6
// speedup vs baseline: 2.2393x; 1.6387x over previous
#include <cuda_runtime.h>
#include <cuda_bf16.h>

#define NUM_FEATURES 64
#define MAX_CAV 5
#define NX 704
#define NY 200
#define NUM_PIXELS (NY * NX)          // 140800
#define TOTAL (MAX_CAV * NUM_PIXELS)  // 704000
#define N_PILLARS 60000
#define NGROUPS (NUM_PIXELS / 4)      // 35200 (= 1100 * 32, exact)

// Inverse map: pixel -> pillar index + 1 (0 = empty).
// Invariant: all-zero before each kernel_launch. Zeroed at module load;
// pp_clear_pixmap restores the invariant at the end of every call by zeroing
// exactly the entries pp_build_pixmap wrote.
__device__ int g_pixmap[TOTAL];

// Kernel A: scatter (pillar+1) into the pixmap (indices are a permutation -> no collisions).
__global__ void __launch_bounds__(256) pp_build_pixmap(const int* __restrict__ vc)
{
    int n = blockIdx.x * blockDim.x + threadIdx.x;
    if (n >= N_PILLARS) return;
    int4 co = __ldg(reinterpret_cast<const int4*>(vc) + n);  // (b, z, y, x)
    g_pixmap[co.x * NUM_PIXELS + co.z * NX + co.w] = n + 1;
}

// Kernel C: zero the occupied pixmap entries (runs after the gather).
__global__ void __launch_bounds__(256) pp_clear_pixmap(const int* __restrict__ vc)
{
    int n = blockIdx.x * blockDim.x + threadIdx.x;
    if (n >= N_PILLARS) return;
    int4 co = __ldg(reinterpret_cast<const int4*>(vc) + n);
    g_pixmap[co.x * NUM_PIXELS + co.z * NX + co.w] = 0;
}

// Kernel B: streaming gather, branchless.
//   thread = (b, 4-pixel group g, channel octet cy): writes 8 channel planes
//   for 4 pixels = 8 x float4 stores (each warp store = 512B contiguous).
//   Pixmap entry loaded once per 8 channels. Feature loads are predicated-by-
//   selection: empty sub-pixels load pillar 0's row (L1 broadcast) and select 0.
__global__ void __launch_bounds__(256) pp_gather(
    const float* __restrict__ feat,   // [N, 64]
    float*       __restrict__ out)    // [5, 64, 200, 704]
{
    int lane = threadIdx.x & 31;
    int w    = threadIdx.x >> 5;                 // 0..7
    int g    = blockIdx.x * 32 + lane;           // 4-pixel group 0..NGROUPS-1
    int cy   = (blockIdx.y * 8 + w);             // channel octet 0..7 -> wait, see grid
    int b    = blockIdx.z;

    // grid.y = 1: the 8 warps of a block ARE the 8 channel octets.
    // cy in 0..7, channels [8*cy, 8*cy+8)

    int4 pm = __ldg(reinterpret_cast<const int4*>(g_pixmap)
                    + (size_t)b * NGROUPS + g);

    const float4* featv = reinterpret_cast<const float4*>(feat);
    const float4 zero = make_float4(0.f, 0.f, 0.f, 0.f);

    // Per sub-pixel: load channels [8cy, 8cy+8) of its pillar (2 float4 = 32B).
    float4 lo[4], hi[4];
    {
        int p[4] = { pm.x, pm.y, pm.z, pm.w };
        #pragma unroll
        for (int j = 0; j < 4; j++) {
            int nn = (p[j] > 0) ? (p[j] - 1) : 0;
            size_t base = (size_t)nn * (NUM_FEATURES / 4) + 2 * cy;
            float4 l = __ldg(featv + base);
            float4 h = __ldg(featv + base + 1);
            bool valid = (p[j] > 0);
            lo[j] = valid ? l : zero;
            hi[j] = valid ? h : zero;
        }
    }

    // Assemble + store: channel 8*cy + k, k = 0..7.
    float4* obase = reinterpret_cast<float4*>(out)
                  + ((size_t)b * NUM_FEATURES + 8 * cy) * NGROUPS + g;

    obase[0 * NGROUPS] = make_float4(lo[0].x, lo[1].x, lo[2].x, lo[3].x);
    obase[1 * NGROUPS] = make_float4(lo[0].y, lo[1].y, lo[2].y, lo[3].y);
    obase[2 * NGROUPS] = make_float4(lo[0].z, lo[1].z, lo[2].z, lo[3].z);
    obase[3 * NGROUPS] = make_float4(lo[0].w, lo[1].w, lo[2].w, lo[3].w);
    obase[4 * NGROUPS] = make_float4(hi[0].x, hi[1].x, hi[2].x, hi[3].x);
    obase[5 * NGROUPS] = make_float4(hi[0].y, hi[1].y, hi[2].y, hi[3].y);
    obase[6 * NGROUPS] = make_float4(hi[0].z, hi[1].z, hi[2].z, hi[3].z);
    obase[7 * NGROUPS] = make_float4(hi[0].w, hi[1].w, hi[2].w, hi[3].w);
}

extern "C" void kernel_launch(void* const* d_in, const int* in_sizes, int n_in,
                              void* d_out, int out_size)
{
    const int*   vc   = (const int*)d_in[0];    // voxel_coords int32 [60000, 4]
    const float* feat = (const float*)d_in[1];  // pillar_features f32 [60000, 64]
    float* out = (float*)d_out;                 // [5, 64, 200, 704] f32

    pp_build_pixmap<<<(N_PILLARS + 255) / 256, 256>>>(vc);

    // Block = 256 threads = 8 warps = 8 channel octets for 32 pixel-groups.
    dim3 grid(NGROUPS / 32, 1, MAX_CAV);   // (1100, 1, 5)
    pp_gather<<<grid, 256>>>(feat, out);

    pp_clear_pixmap<<<(N_PILLARS + 255) / 256, 256>>>(vc);
}

// round 7
// speedup vs baseline: 2.4350x; 1.0874x over previous
#include <cuda_runtime.h>
#include <cuda_bf16.h>

#define NUM_FEATURES 64
#define MAX_CAV 5
#define NX 704
#define NY 200
#define NUM_PIXELS (NY * NX)          // 140800
#define TOTAL (MAX_CAV * NUM_PIXELS)  // 704000
#define N_PILLARS 60000
#define NGROUPS (NUM_PIXELS / 4)      // 35200 (= 1100 * 32, exact)

// Inverse map: pixel -> pillar index + 1 (0 = empty).
// Invariant: all-zero before each kernel_launch. Zeroed at module load; the
// gather kernel zeroes every nonzero entry it consumes, restoring the
// invariant each call. Output is a pure function of the current inputs.
__device__ int g_pixmap[TOTAL];

// Kernel A: scatter (pillar+1) into the pixmap (indices are a permutation -> no collisions).
__global__ void __launch_bounds__(256) pp_build_pixmap(const int* __restrict__ vc)
{
    int n = blockIdx.x * blockDim.x + threadIdx.x;
    if (n >= N_PILLARS) return;
    int4 co = __ldg(reinterpret_cast<const int4*>(vc) + n);  // (b, z, y, x)
    g_pixmap[co.x * NUM_PIXELS + co.z * NX + co.w] = n + 1;
}

// Kernel B: streaming gather + self-clearing pixmap.
//   block = (b, 32 consecutive 4-pixel groups); warp w = channel octet cy.
//   Warp 0 stages the 32 pixmap int4s into smem and zeroes the nonzero ones.
//   Each thread writes 8 channel planes for its 4 pixels = 8 x float4 stores
//   (each warp store = 512B contiguous). Feature loads are branchless:
//   empty sub-pixels load pillar 0's row (L1 broadcast) and select zero.
__global__ void __launch_bounds__(256) pp_gather(
    const float* __restrict__ feat,   // [N, 64]
    float*       __restrict__ out)    // [5, 64, 200, 704]
{
    __shared__ int4 s_pm[32];

    int lane = threadIdx.x & 31;
    int w    = threadIdx.x >> 5;                 // 0..7 = channel octet
    int g    = blockIdx.x * 32 + lane;           // 4-pixel group 0..NGROUPS-1
    int b    = blockIdx.z;                       // 0..4

    if (w == 0) {
        int4* pmp = reinterpret_cast<int4*>(g_pixmap) + (size_t)b * NGROUPS + g;
        int4 pm = *pmp;
        s_pm[lane] = pm;
        if ((pm.x | pm.y | pm.z | pm.w) != 0)
            *pmp = make_int4(0, 0, 0, 0);        // self-clear for next call
    }
    __syncthreads();

    int4 pm = s_pm[lane];
    int cy = w;                                  // channels [8*cy, 8*cy+8)

    const float4* featv = reinterpret_cast<const float4*>(feat);
    const float4 zero = make_float4(0.f, 0.f, 0.f, 0.f);

    float4 lo[4], hi[4];
    {
        int p[4] = { pm.x, pm.y, pm.z, pm.w };
        #pragma unroll
        for (int j = 0; j < 4; j++) {
            int nn = (p[j] > 0) ? (p[j] - 1) : 0;
            size_t base = (size_t)nn * (NUM_FEATURES / 4) + 2 * cy;
            float4 l = __ldg(featv + base);
            float4 h = __ldg(featv + base + 1);
            bool valid = (p[j] > 0);
            lo[j] = valid ? l : zero;
            hi[j] = valid ? h : zero;
        }
    }

    float4* obase = reinterpret_cast<float4*>(out)
                  + ((size_t)b * NUM_FEATURES + 8 * cy) * NGROUPS + g;

    obase[0 * NGROUPS] = make_float4(lo[0].x, lo[1].x, lo[2].x, lo[3].x);
    obase[1 * NGROUPS] = make_float4(lo[0].y, lo[1].y, lo[2].y, lo[3].y);
    obase[2 * NGROUPS] = make_float4(lo[0].z, lo[1].z, lo[2].z, lo[3].z);
    obase[3 * NGROUPS] = make_float4(lo[0].w, lo[1].w, lo[2].w, lo[3].w);
    obase[4 * NGROUPS] = make_float4(hi[0].x, hi[1].x, hi[2].x, hi[3].x);
    obase[5 * NGROUPS] = make_float4(hi[0].y, hi[1].y, hi[2].y, hi[3].y);
    obase[6 * NGROUPS] = make_float4(hi[0].z, hi[1].z, hi[2].z, hi[3].z);
    obase[7 * NGROUPS] = make_float4(hi[0].w, hi[1].w, hi[2].w, hi[3].w);
}

extern "C" void kernel_launch(void* const* d_in, const int* in_sizes, int n_in,
                              void* d_out, int out_size)
{
    const int*   vc   = (const int*)d_in[0];    // voxel_coords int32 [60000, 4]
    const float* feat = (const float*)d_in[1];  // pillar_features f32 [60000, 64]
    float* out = (float*)d_out;                 // [5, 64, 200, 704] f32

    pp_build_pixmap<<<(N_PILLARS + 255) / 256, 256>>>(vc);

    dim3 grid(NGROUPS / 32, 1, MAX_CAV);   // (1100, 1, 5)
    pp_gather<<<grid, 256>>>(feat, out);
}

// round 8
// speedup vs baseline: 2.7908x; 1.1461x over previous
#include <cuda_runtime.h>
#include <cuda_bf16.h>

#define NUM_FEATURES 64
#define MAX_CAV 5
#define NX 704
#define NY 200
#define NUM_PIXELS (NY * NX)          // 140800
#define TOTAL (MAX_CAV * NUM_PIXELS)  // 704000
#define N_PILLARS 60000
#define NGROUPS (NUM_PIXELS / 4)      // 35200 (= 1100 * 32, exact)

// Inverse map: pixel -> pillar index + 1 (0 = empty).
// Invariant: all-zero before each kernel_launch. Zeroed at module load; the
// gather kernel zeroes every nonzero entry it consumes, restoring the
// invariant each call. Output is a pure function of the current inputs.
__device__ int g_pixmap[TOTAL];

// Kernel A: scatter (pillar+1) into the pixmap (indices are a permutation -> no collisions).
__global__ void __launch_bounds__(256) pp_build_pixmap(const int* __restrict__ vc)
{
    int n = blockIdx.x * blockDim.x + threadIdx.x;
    if (n >= N_PILLARS) return;
    int4 co = __ldg(reinterpret_cast<const int4*>(vc) + n);  // (b, z, y, x)
    g_pixmap[co.x * NUM_PIXELS + co.z * NX + co.w] = n + 1;
}

// Kernel B: streaming gather + self-clearing pixmap.
//   block = (b, 32 consecutive 4-pixel groups); warp w = channel octet.
//   Two half-transposes per thread (4 channels each) to keep <=42 regs live
//   -> 6 blocks/SM occupancy. Warp stores are 512B contiguous float4.
__global__ void __launch_bounds__(256, 6) pp_gather(
    const float* __restrict__ feat,   // [N, 64]
    float*       __restrict__ out)    // [5, 64, 200, 704]
{
    __shared__ int4 s_pm[32];

    int lane = threadIdx.x & 31;
    int w    = threadIdx.x >> 5;                 // 0..7 = channel octet
    int g    = blockIdx.x * 32 + lane;           // 4-pixel group 0..NGROUPS-1
    int b    = blockIdx.z;                       // 0..4

    if (w == 0) {
        int4* pmp = reinterpret_cast<int4*>(g_pixmap) + (size_t)b * NGROUPS + g;
        int4 pm = *pmp;
        s_pm[lane] = pm;
        if ((pm.x | pm.y | pm.z | pm.w) != 0)
            *pmp = make_int4(0, 0, 0, 0);        // self-clear for next call
    }
    __syncthreads();

    int4 pmv = s_pm[lane];
    int p[4] = { pmv.x, pmv.y, pmv.z, pmv.w };

    const float4* featv = reinterpret_cast<const float4*>(feat);
    const float4 zero = make_float4(0.f, 0.f, 0.f, 0.f);

    // Per sub-pixel feature-row base (in float4 units), clamped to pillar 0
    // for empty sub-pixels (harmless broadcast load, selected to zero).
    size_t fb[4];
    #pragma unroll
    for (int j = 0; j < 4; j++) {
        int nn = (p[j] > 0) ? (p[j] - 1) : 0;
        fb[j] = (size_t)nn * (NUM_FEATURES / 4) + 2 * w;
    }

    float4* obase = reinterpret_cast<float4*>(out)
                  + ((size_t)b * NUM_FEATURES + 8 * w) * NGROUPS + g;

    // Half 1: channels [8w, 8w+4)
    {
        float4 v[4];
        #pragma unroll
        for (int j = 0; j < 4; j++) {
            float4 l = __ldg(featv + fb[j]);
            v[j] = (p[j] > 0) ? l : zero;
        }
        obase[0 * NGROUPS] = make_float4(v[0].x, v[1].x, v[2].x, v[3].x);
        obase[1 * NGROUPS] = make_float4(v[0].y, v[1].y, v[2].y, v[3].y);
        obase[2 * NGROUPS] = make_float4(v[0].z, v[1].z, v[2].z, v[3].z);
        obase[3 * NGROUPS] = make_float4(v[0].w, v[1].w, v[2].w, v[3].w);
    }

    // Half 2: channels [8w+4, 8w+8)
    {
        float4 v[4];
        #pragma unroll
        for (int j = 0; j < 4; j++) {
            float4 h = __ldg(featv + fb[j] + 1);
            v[j] = (p[j] > 0) ? h : zero;
        }
        obase[4 * NGROUPS] = make_float4(v[0].x, v[1].x, v[2].x, v[3].x);
        obase[5 * NGROUPS] = make_float4(v[0].y, v[1].y, v[2].y, v[3].y);
        obase[6 * NGROUPS] = make_float4(v[0].z, v[1].z, v[2].z, v[3].z);
        obase[7 * NGROUPS] = make_float4(v[0].w, v[1].w, v[2].w, v[3].w);
    }
}

extern "C" void kernel_launch(void* const* d_in, const int* in_sizes, int n_in,
                              void* d_out, int out_size)
{
    const int*   vc   = (const int*)d_in[0];    // voxel_coords int32 [60000, 4]
    const float* feat = (const float*)d_in[1];  // pillar_features f32 [60000, 64]
    float* out = (float*)d_out;                 // [5, 64, 200, 704] f32

    pp_build_pixmap<<<(N_PILLARS + 255) / 256, 256>>>(vc);

    dim3 grid(NGROUPS / 32, 1, MAX_CAV);   // (1100, 1, 5)
    pp_gather<<<grid, 256>>>(feat, out);
}

// round 9
// speedup vs baseline: 2.9140x; 1.0442x over previous
#include <cuda_runtime.h>
#include <cuda_bf16.h>

#define NUM_FEATURES 64
#define MAX_CAV 5
#define NX 704
#define NY 200
#define NUM_PIXELS (NY * NX)          // 140800
#define TOTAL (MAX_CAV * NUM_PIXELS)  // 704000
#define N_PILLARS 60000
#define NGROUPS (NUM_PIXELS / 4)      // 35200 (= 1100 * 32, exact)

// Inverse map: pixel -> pillar index + 1 (0 = empty).
// Invariant: all-zero before each kernel_launch. Zeroed at module load; the
// gather kernel zeroes every nonzero entry it consumes, restoring the
// invariant each call. Output is a pure function of the current inputs.
__device__ int g_pixmap[TOTAL];

// Kernel A: scatter (pillar+1) into the pixmap (indices are a permutation -> no collisions).
__global__ void __launch_bounds__(256) pp_build_pixmap(const int* __restrict__ vc)
{
    int n = blockIdx.x * blockDim.x + threadIdx.x;
    if (n >= N_PILLARS) return;
    int4 co = __ldg(reinterpret_cast<const int4*>(vc) + n);  // (b, z, y, x)
    g_pixmap[co.x * NUM_PIXELS + co.z * NX + co.w] = n + 1;
}

// Kernel B: streaming gather + self-clearing pixmap.
//   block = (b, 32 consecutive 4-pixel groups); warp w = channel octet.
//   Two half-transposes per thread, all-int32 index math, <=32 regs target
//   -> 8 blocks/SM. Warp stores are 512B contiguous float4.
__global__ void __launch_bounds__(256, 8) pp_gather(
    const float* __restrict__ feat,   // [N, 64]
    float*       __restrict__ out)    // [5, 64, 200, 704]
{
    __shared__ int4 s_pm[32];

    int lane = threadIdx.x & 31;
    int w    = threadIdx.x >> 5;                 // 0..7 = channel octet
    int g    = blockIdx.x * 32 + lane;           // 4-pixel group 0..NGROUPS-1
    int b    = blockIdx.z;                       // 0..4

    if (w == 0) {
        int4* pmp = reinterpret_cast<int4*>(g_pixmap) + b * NGROUPS + g;
        int4 pm = *pmp;
        s_pm[lane] = pm;
        if ((pm.x | pm.y | pm.z | pm.w) != 0)
            *pmp = make_int4(0, 0, 0, 0);        // self-clear for next call
    }
    __syncthreads();

    int4 pmv = s_pm[lane];
    int p0 = pmv.x, p1 = pmv.y, p2 = pmv.z, p3 = pmv.w;

    const float4* featv = reinterpret_cast<const float4*>(feat);
    const float4 zero = make_float4(0.f, 0.f, 0.f, 0.f);

    // 32-bit feature-row offsets (float4 units), clamped to pillar 0 for
    // empty sub-pixels (broadcast L1 hit, selected to zero).
    int c2 = 2 * w;
    int f0 = (p0 > 0 ? (p0 - 1) : 0) * (NUM_FEATURES / 4) + c2;
    int f1 = (p1 > 0 ? (p1 - 1) : 0) * (NUM_FEATURES / 4) + c2;
    int f2 = (p2 > 0 ? (p2 - 1) : 0) * (NUM_FEATURES / 4) + c2;
    int f3 = (p3 > 0 ? (p3 - 1) : 0) * (NUM_FEATURES / 4) + c2;

    // 32-bit output offset (float4 units): max 11.26M, fits easily.
    int ob = (b * NUM_FEATURES + 8 * w) * NGROUPS + g;
    float4* obase = reinterpret_cast<float4*>(out) + ob;

    // Half 1: channels [8w, 8w+4)
    {
        float4 v0 = (p0 > 0) ? __ldg(featv + f0) : zero;
        float4 v1 = (p1 > 0) ? __ldg(featv + f1) : zero;
        float4 v2 = (p2 > 0) ? __ldg(featv + f2) : zero;
        float4 v3 = (p3 > 0) ? __ldg(featv + f3) : zero;
        obase[0 * NGROUPS] = make_float4(v0.x, v1.x, v2.x, v3.x);
        obase[1 * NGROUPS] = make_float4(v0.y, v1.y, v2.y, v3.y);
        obase[2 * NGROUPS] = make_float4(v0.z, v1.z, v2.z, v3.z);
        obase[3 * NGROUPS] = make_float4(v0.w, v1.w, v2.w, v3.w);
    }

    // Half 2: channels [8w+4, 8w+8)
    {
        float4 v0 = (p0 > 0) ? __ldg(featv + f0 + 1) : zero;
        float4 v1 = (p1 > 0) ? __ldg(featv + f1 + 1) : zero;
        float4 v2 = (p2 > 0) ? __ldg(featv + f2 + 1) : zero;
        float4 v3 = (p3 > 0) ? __ldg(featv + f3 + 1) : zero;
        obase[4 * NGROUPS] = make_float4(v0.x, v1.x, v2.x, v3.x);
        obase[5 * NGROUPS] = make_float4(v0.y, v1.y, v2.y, v3.y);
        obase[6 * NGROUPS] = make_float4(v0.z, v1.z, v2.z, v3.z);
        obase[7 * NGROUPS] = make_float4(v0.w, v1.w, v2.w, v3.w);
    }
}

extern "C" void kernel_launch(void* const* d_in, const int* in_sizes, int n_in,
                              void* d_out, int out_size)
{
    const int*   vc   = (const int*)d_in[0];    // voxel_coords int32 [60000, 4]
    const float* feat = (const float*)d_in[1];  // pillar_features f32 [60000, 64]
    float* out = (float*)d_out;                 // [5, 64, 200, 704] f32

    pp_build_pixmap<<<(N_PILLARS + 255) / 256, 256>>>(vc);

    dim3 grid(NGROUPS / 32, 1, MAX_CAV);   // (1100, 1, 5)
    pp_gather<<<grid, 256>>>(feat, out);
}